// round 15
// baseline (speedup 1.0000x reference)
#include <cuda_runtime.h>
#include <cuda_fp16.h>
#include <cstdint>

#define DNODES 128
#define HID    512
#define NSAMP  2048
#define TM     64
#define THREADS 256
#define NTILES 40           // 8 (L0: K=128 x 2 chunks) + 32 (L1: K=512 x 2 chunks), KT=32

// smem byte offsets
#define APH_B   0                     // h1 packed: 32 ksteps x 4 mf x 512B = 64KB
#define APX_B   49152                 // x packed: 8 ksteps x 4 mf x 512B (aliases APH ksteps 24..31)
#define W2_B    65536                 // 512 f32
#define OUTS_B  67584                 // 64 f32
#define BSTG_B  67840                 // per-warp B ring: 8 warps x 2 slots x 2KB = 32KB
#define SMEMB   100608                // x2 blocks = 196.6KB <= 227KB -> 2 blocks/SM

// packed fp16 weights, fragment-major: [d][c(2)][kt][s(2)][q(16)][lane(32)] x 16B
__device__ __half g_Wp0[(size_t)DNODES * 2 * 4  * 2 * 16 * 32 * 8];
__device__ __half g_Wp1[(size_t)DNODES * 2 * 16 * 2 * 16 * 32 * 8];

// uint4 totals and block counts (256 threads/block, 1 uint4/thread)
#define TOT0 ((size_t)DNODES * 2 * 4  * 2 * 16 * 32)   // 1,048,576
#define TOT1 ((size_t)DNODES * 2 * 16 * 2 * 16 * 32)   // 4,194,304
#define NB0  4096            // TOT0 / 256
#define NB1  16384           // TOT1 / 256

__device__ __forceinline__ float leaky(float x) { return x > 0.0f ? x : 0.01f * x; }

__device__ __forceinline__ void mma_f16(float c[4], uint32_t a0, uint32_t a1,
                                        uint32_t a2, uint32_t a3,
                                        uint32_t b0, uint32_t b1) {
    asm volatile(
        "mma.sync.aligned.m16n8k16.row.col.f32.f16.f16.f32 "
        "{%0,%1,%2,%3},{%4,%5,%6,%7},{%8,%9},{%0,%1,%2,%3};"
        : "+f"(c[0]), "+f"(c[1]), "+f"(c[2]), "+f"(c[3])
        : "r"(a0), "r"(a1), "r"(a2), "r"(a3), "r"(b0), "r"(b1));
}

__device__ __forceinline__ uint32_t smem_u32(const void* p) {
    uint32_t a;
    asm("{ .reg .u64 t; cvta.to.shared.u64 t, %1; cvt.u32.u64 %0, t; }" : "=r"(a) : "l"(p));
    return a;
}
#define CP_ASYNC16(sa, gp) \
    asm volatile("cp.async.cg.shared.global [%0], [%1], 16;" :: "r"((uint32_t)(sa)), "l"(gp) : "memory")
#define CP_COMMIT() asm volatile("cp.async.commit_group;" ::: "memory")
#define CP_WAIT0()  asm volatile("cp.async.wait_group 0;" ::: "memory")

__device__ __forceinline__ uint32_t pack_h2(float lo, float hi) {
    __half2 h = __halves2half2(__float2half_rn(lo), __float2half_rn(hi));
    return *reinterpret_cast<uint32_t*>(&h);
}

// ---------- merged prepass: ONE launch packs both W0 and W1 (fragment-major fp16) ----------
__device__ __forceinline__ void pack_one(const float* __restrict__ W, __half* __restrict__ Wp,
                                         size_t idx, size_t total, int KTOT, int LOGKT) {
    if (idx >= total) return;
    int lane = (int)(idx & 31);
    int q    = (int)((idx >> 5) & 15);
    int s    = (int)((idx >> 9) & 1);
    int kt   = (int)((idx >> 10) & ((KTOT / 32) - 1));
    int c    = (int)((idx >> (10 + LOGKT)) & 1);
    int d    = (int)(idx >> (11 + LOGKT));
    int g = lane >> 2, t4 = lane & 3;
    int colb = c * 256 + (q >> 2) * 64 + (q & 3) * 16 + g;
    int kb = kt * 32 + s * 16 + 2 * t4;
    const float* src = W + (size_t)d * KTOT * HID;
    uint32_t r[4];
#pragma unroll
    for (int f = 0; f < 2; f++)
#pragma unroll
        for (int hb = 0; hb < 2; hb++) {
            int k = kb + hb * 8;
            int col = colb + f * 8;
            r[f * 2 + hb] = pack_h2(src[(size_t)k * HID + col],
                                    src[(size_t)(k + 1) * HID + col]);
        }
    reinterpret_cast<uint4*>(Wp)[idx] = make_uint4(r[0], r[1], r[2], r[3]);
}

__global__ void pack_all(const float* __restrict__ W0, const float* __restrict__ W1) {
    if (blockIdx.x < NB0) {
        size_t idx = (size_t)blockIdx.x * 256 + threadIdx.x;
        pack_one(W0, g_Wp0, idx, TOT0, DNODES, 2);
    } else {
        size_t idx = (size_t)(blockIdx.x - NB0) * 256 + threadIdx.x;
        pack_one(W1, g_Wp1, idx, TOT1, HID, 4);
    }
}

// ---------- main fused kernel: 8 warps, 64x32 warp tile, per-warp cp.async B ring ----------
extern __shared__ char smc[];

__global__ void __launch_bounds__(THREADS, 2)
grandag_f16_kernel(const float* __restrict__ x,
                   const float* __restrict__ W2,
                   float* __restrict__ out) {
    const int tid = threadIdx.x;
    const int wn = tid >> 5;      // 8 N-warps (32 cols each), each owns all 64 rows
    const int lane = tid & 31;
    const int g = lane >> 2;
    const int t4 = lane & 3;
    const int d = blockIdx.y;
    const int n0 = blockIdx.x * TM;
    const uint32_t sb = smem_u32(smc);
    float* smf = reinterpret_cast<float*>(smc);

    if (tid < TM) smf[OUTS_B / 4 + tid] = 0.0f;
    for (int i = tid; i < HID; i += THREADS)
        smf[W2_B / 4 + i] = W2[(size_t)d * HID + i];

    // pack masked x -> APX fragment-major: [kstep(8)][mf(4)][512B] (kstep = wn)
    {
        const float* xb = x + (size_t)n0 * DNODES;
        int k0 = wn * 16 + 2 * t4;
#pragma unroll
        for (int mf = 0; mf < 4; mf++) {
            int r0 = mf * 16 + g, r1 = r0 + 8;
            float v[8];
            v[0] = xb[(size_t)r0 * DNODES + k0];     v[1] = xb[(size_t)r0 * DNODES + k0 + 1];
            v[2] = xb[(size_t)r1 * DNODES + k0];     v[3] = xb[(size_t)r1 * DNODES + k0 + 1];
            v[4] = xb[(size_t)r0 * DNODES + k0 + 8]; v[5] = xb[(size_t)r0 * DNODES + k0 + 9];
            v[6] = xb[(size_t)r1 * DNODES + k0 + 8]; v[7] = xb[(size_t)r1 * DNODES + k0 + 9];
            if (k0 == d)     { v[0] = 0.f; v[2] = 0.f; }
            if (k0 + 1 == d) { v[1] = 0.f; v[3] = 0.f; }
            if (k0 + 8 == d) { v[4] = 0.f; v[6] = 0.f; }
            if (k0 + 9 == d) { v[5] = 0.f; v[7] = 0.f; }
            uint4 u = make_uint4(pack_h2(v[0], v[1]), pack_h2(v[2], v[3]),
                                 pack_h2(v[4], v[5]), pack_h2(v[6], v[7]));
            *reinterpret_cast<uint4*>(smc + APX_B + (wn * 4 + mf) * 512 + lane * 16) = u;
        }
    }
    __syncthreads();   // x pack + w2 + outs visible to all warps

    // precomputed per-d linear B bases (uint4 units); tile stride = 1024 uint4 (16KB)
    const uint4* w0b = reinterpret_cast<const uint4*>(g_Wp0) + (size_t)d * 2 * 4 * 1024 + lane;
    const uint4* w1b = reinterpret_cast<const uint4*>(g_Wp1) + (size_t)d * 2 * 16 * 1024 + lane;
    auto bbase = [&](int t) -> const uint4* {
        return (t < 8) ? (w0b + t * 1024) : (w1b + (t - 8) * 1024);
    };
    // stage this warp's 2KB B tile for t into slot (t&1) of its private ring
    const uint32_t bwarp = sb + BSTG_B + (uint32_t)wn * 4096 + (uint32_t)lane * 16;
    auto bstage = [&](int t) {
        const uint4* gsrc = bbase(t);
        uint32_t dstb = bwarp + (uint32_t)(t & 1) * 2048;
#pragma unroll
        for (int i = 0; i < 4; i++)    // i = s*2 + p
            CP_ASYNC16(dstb + i * 512, gsrc + ((i >> 1) * 16 + wn * 2 + (i & 1)) * 32);
        CP_COMMIT();
    };

    bstage(0);

    float acc[4][4][4];                 // 64 rows (4 mf) x 32 cols (4 n8)
    float pr[8] = {0.f,0.f,0.f,0.f,0.f,0.f,0.f,0.f};

#pragma unroll 1
    for (int t = 0; t < NTILES; t++) {
        CP_WAIT0();        // stage(t) complete (issued a full tile ago)
        __syncwarp();
        if (t + 1 < NTILES) bstage(t + 1);   // full-tile prefetch distance, other slot

        bool first = (t < 8) ? ((t & 3) == 0) : (((t - 8) & 15) == 0);
        if (first) {
#pragma unroll
            for (int mf = 0; mf < 4; mf++)
#pragma unroll
                for (int s = 0; s < 4; s++)
#pragma unroll
                    for (int j = 0; j < 4; j++) acc[mf][s][j] = 0.f;
        }

        const int abase = (t < 8) ? (APX_B + (t & 3) * 4096)
                                  : (APH_B + ((t - 8) & 15) * 4096);
        const char* bslot = smc + BSTG_B + wn * 4096 + (t & 1) * 2048;

#pragma unroll
        for (int ks = 0; ks < 2; ks++) {
            uint4 a[4];
#pragma unroll
            for (int mf = 0; mf < 4; mf++)
                a[mf] = *reinterpret_cast<const uint4*>(
                    smc + abase + ks * 2048 + mf * 512 + lane * 16);
#pragma unroll
            for (int p = 0; p < 2; p++) {
                uint4 b = *reinterpret_cast<const uint4*>(
                    bslot + ((ks * 2 + p) * 32 + lane) * 16);
#pragma unroll
                for (int mf = 0; mf < 4; mf++) {
                    mma_f16(acc[mf][2 * p],     a[mf].x, a[mf].y, a[mf].z, a[mf].w, b.x, b.y);
                    mma_f16(acc[mf][2 * p + 1], a[mf].x, a[mf].y, a[mf].z, a[mf].w, b.z, b.w);
                }
            }
        }

        // L0 chunk epilogue: leaky -> fp16 -> APH fragment-major (conflict-free STS.128)
        if (t == 3 || t == 7) {
            if (t == 7) __syncthreads();   // all warps done reading aliased APX region
            int c = t >> 2;
#pragma unroll
            for (int mf = 0; mf < 4; mf++) {
#pragma unroll
                for (int p = 0; p < 2; p++) {
                    int K = c * 16 + wn * 2 + p;
                    int se = 2 * p, so = 2 * p + 1;
                    uint4 u = make_uint4(
                        pack_h2(leaky(acc[mf][se][0]), leaky(acc[mf][se][1])),
                        pack_h2(leaky(acc[mf][se][2]), leaky(acc[mf][se][3])),
                        pack_h2(leaky(acc[mf][so][0]), leaky(acc[mf][so][1])),
                        pack_h2(leaky(acc[mf][so][2]), leaky(acc[mf][so][3])));
                    *reinterpret_cast<uint4*>(
                        smc + APH_B + (K * 4 + mf) * 512 + lane * 16) = u;
                }
            }
            if (t == 7) __syncthreads();   // h1 complete before L1 A-reads
        }
        // L1 chunk epilogue: fused layer-2 dot (fp32)
        if (t == 23 || t == 39) {
            int c = (t - 8) >> 4;
#pragma unroll
            for (int mf = 0; mf < 4; mf++)
#pragma unroll
                for (int s = 0; s < 4; s++) {
                    int n = c * 256 + wn * 32 + 8 * s + 2 * t4;
                    float w2a = smf[W2_B / 4 + n], w2b = smf[W2_B / 4 + n + 1];
                    pr[mf * 2 + 0] += leaky(acc[mf][s][0]) * w2a + leaky(acc[mf][s][1]) * w2b;
                    pr[mf * 2 + 1] += leaky(acc[mf][s][2]) * w2a + leaky(acc[mf][s][3]) * w2b;
                }
        }
    }

#pragma unroll
    for (int j = 0; j < 8; j++) {
        pr[j] += __shfl_xor_sync(0xffffffffu, pr[j], 1);
        pr[j] += __shfl_xor_sync(0xffffffffu, pr[j], 2);
    }
    if (t4 == 0) {
#pragma unroll
        for (int mf = 0; mf < 4; mf++) {
            int R = mf * 16;
            atomicAdd(&smf[OUTS_B / 4 + R + g], pr[mf * 2 + 0]);
            atomicAdd(&smf[OUTS_B / 4 + R + g + 8], pr[mf * 2 + 1]);
        }
    }
    __syncthreads();
    if (tid < TM)
        out[(size_t)(n0 + tid) * DNODES + d] = smf[OUTS_B / 4 + tid];
}

extern "C" void kernel_launch(void* const* d_in, const int* in_sizes, int n_in,
                              void* d_out, int out_size) {
    (void)in_sizes; (void)n_in; (void)out_size;
    const float* x  = (const float*)d_in[0];
    const float* W0 = (const float*)d_in[1];
    const float* W1 = (const float*)d_in[2];
    const float* W2 = (const float*)d_in[3];
    float* out = (float*)d_out;

    pack_all<<<NB0 + NB1, 256>>>(W0, W1);

    cudaFuncSetAttribute(grandag_f16_kernel,
                         cudaFuncAttributeMaxDynamicSharedMemorySize, SMEMB);
    dim3 grid(NSAMP / TM, DNODES);   // x fastest: same-d blocks co-resident (L2/L1 weight reuse)
    grandag_f16_kernel<<<grid, THREADS, SMEMB>>>(x, W2, out);
}

// round 16
// speedup vs baseline: 1.0557x; 1.0557x over previous
#include <cuda_runtime.h>
#include <cuda_fp16.h>
#include <cstdint>

#define DNODES 128
#define HID    512
#define NSAMP  2048
#define TM     64
#define THREADS 256
#define NTILES 40           // 8 (L0: K=128 x 2 chunks) + 32 (L1: K=512 x 2 chunks), KT=32

// smem byte offsets
#define APH_B   0                     // h1 packed: 32 ksteps x 4 mf x 512B = 64KB
#define APX_B   49152                 // x packed: 8 ksteps x 4 mf x 512B (aliases APH ksteps 24..31)
#define W2_B    65536                 // 512 f32
#define OUTS_B  67584                 // 64 f32
#define BSTG_B  67840                 // per-warp B ring: 8 warps x 2 slots x 2KB = 32KB
#define SMEMB   100608                // x2 blocks = 196.6KB <= 227KB -> 2 blocks/SM

// packed fp16 weights, fragment-major: [d][c(2)][kt][s(2)][q(16)][lane(32)] x 16B
__device__ __half g_Wp0[(size_t)DNODES * 2 * 4  * 2 * 16 * 32 * 8];
__device__ __half g_Wp1[(size_t)DNODES * 2 * 16 * 2 * 16 * 32 * 8];

// uint4 totals; prepass: each thread writes 2 uint4 (idx, idx+half) for 2x MLP
#define TOT0 ((size_t)DNODES * 2 * 4  * 2 * 16 * 32)   // 1,048,576
#define TOT1 ((size_t)DNODES * 2 * 16 * 2 * 16 * 32)   // 4,194,304
#define NB0H 2048            // (TOT0/2) / 256
#define NB1H 8192            // (TOT1/2) / 256

__device__ __forceinline__ float leaky(float x) { return x > 0.0f ? x : 0.01f * x; }

__device__ __forceinline__ void mma_f16(float c[4], uint32_t a0, uint32_t a1,
                                        uint32_t a2, uint32_t a3,
                                        uint32_t b0, uint32_t b1) {
    asm volatile(
        "mma.sync.aligned.m16n8k16.row.col.f32.f16.f16.f32 "
        "{%0,%1,%2,%3},{%4,%5,%6,%7},{%8,%9},{%0,%1,%2,%3};"
        : "+f"(c[0]), "+f"(c[1]), "+f"(c[2]), "+f"(c[3])
        : "r"(a0), "r"(a1), "r"(a2), "r"(a3), "r"(b0), "r"(b1));
}

__device__ __forceinline__ uint32_t smem_u32(const void* p) {
    uint32_t a;
    asm("{ .reg .u64 t; cvta.to.shared.u64 t, %1; cvt.u32.u64 %0, t; }" : "=r"(a) : "l"(p));
    return a;
}
#define CP_ASYNC16(sa, gp) \
    asm volatile("cp.async.cg.shared.global [%0], [%1], 16;" :: "r"((uint32_t)(sa)), "l"(gp) : "memory")
#define CP_COMMIT() asm volatile("cp.async.commit_group;" ::: "memory")
#define CP_WAIT0()  asm volatile("cp.async.wait_group 0;" ::: "memory")

__device__ __forceinline__ uint32_t pack_h2(float lo, float hi) {
    __half2 h = __halves2half2(__float2half_rn(lo), __float2half_rn(hi));
    return *reinterpret_cast<uint32_t*>(&h);
}

// ---------- merged prepass: ONE launch packs both W0 and W1 (fragment-major fp16) ----------
__device__ __forceinline__ void pack_one(const float* __restrict__ W, __half* __restrict__ Wp,
                                         size_t idx, size_t total, int KTOT, int LOGKT) {
    if (idx >= total) return;
    int lane = (int)(idx & 31);
    int q    = (int)((idx >> 5) & 15);
    int s    = (int)((idx >> 9) & 1);
    int kt   = (int)((idx >> 10) & ((KTOT / 32) - 1));
    int c    = (int)((idx >> (10 + LOGKT)) & 1);
    int d    = (int)(idx >> (11 + LOGKT));
    int g = lane >> 2, t4 = lane & 3;
    int colb = c * 256 + (q >> 2) * 64 + (q & 3) * 16 + g;
    int kb = kt * 32 + s * 16 + 2 * t4;
    const float* src = W + (size_t)d * KTOT * HID;
    uint32_t r[4];
#pragma unroll
    for (int f = 0; f < 2; f++)
#pragma unroll
        for (int hb = 0; hb < 2; hb++) {
            int k = kb + hb * 8;
            int col = colb + f * 8;
            r[f * 2 + hb] = pack_h2(src[(size_t)k * HID + col],
                                    src[(size_t)(k + 1) * HID + col]);
        }
    reinterpret_cast<uint4*>(Wp)[idx] = make_uint4(r[0], r[1], r[2], r[3]);
}

__global__ void pack_all(const float* __restrict__ W0, const float* __restrict__ W1) {
    if (blockIdx.x < NB0H) {
        size_t idx = (size_t)blockIdx.x * 256 + threadIdx.x;
        pack_one(W0, g_Wp0, idx, TOT0, DNODES, 2);
        pack_one(W0, g_Wp0, idx + TOT0 / 2, TOT0, DNODES, 2);
    } else {
        size_t idx = (size_t)(blockIdx.x - NB0H) * 256 + threadIdx.x;
        pack_one(W1, g_Wp1, idx, TOT1, HID, 4);
        pack_one(W1, g_Wp1, idx + TOT1 / 2, TOT1, HID, 4);
    }
}

// ---------- main fused kernel: 8 warps, 64x32 warp tile, per-warp cp.async B ring ----------
// (byte-exact round-13 champion; do not perturb — schedule is regs=125/128 fragile)
extern __shared__ char smc[];

__global__ void __launch_bounds__(THREADS, 2)
grandag_f16_kernel(const float* __restrict__ x,
                   const float* __restrict__ W2,
                   float* __restrict__ out) {
    const int tid = threadIdx.x;
    const int wn = tid >> 5;      // 8 N-warps (32 cols each), each owns all 64 rows
    const int lane = tid & 31;
    const int g = lane >> 2;
    const int t4 = lane & 3;
    const int d = blockIdx.y;
    const int n0 = blockIdx.x * TM;
    const uint32_t sb = smem_u32(smc);
    float* smf = reinterpret_cast<float*>(smc);

    if (tid < TM) smf[OUTS_B / 4 + tid] = 0.0f;
    for (int i = tid; i < HID; i += THREADS)
        smf[W2_B / 4 + i] = W2[(size_t)d * HID + i];

    // pack masked x -> APX fragment-major: [kstep(8)][mf(4)][512B] (kstep = wn)
    {
        const float* xb = x + (size_t)n0 * DNODES;
        int k0 = wn * 16 + 2 * t4;
#pragma unroll
        for (int mf = 0; mf < 4; mf++) {
            int r0 = mf * 16 + g, r1 = r0 + 8;
            float v[8];
            v[0] = xb[(size_t)r0 * DNODES + k0];     v[1] = xb[(size_t)r0 * DNODES + k0 + 1];
            v[2] = xb[(size_t)r1 * DNODES + k0];     v[3] = xb[(size_t)r1 * DNODES + k0 + 1];
            v[4] = xb[(size_t)r0 * DNODES + k0 + 8]; v[5] = xb[(size_t)r0 * DNODES + k0 + 9];
            v[6] = xb[(size_t)r1 * DNODES + k0 + 8]; v[7] = xb[(size_t)r1 * DNODES + k0 + 9];
            if (k0 == d)     { v[0] = 0.f; v[2] = 0.f; }
            if (k0 + 1 == d) { v[1] = 0.f; v[3] = 0.f; }
            if (k0 + 8 == d) { v[4] = 0.f; v[6] = 0.f; }
            if (k0 + 9 == d) { v[5] = 0.f; v[7] = 0.f; }
            uint4 u = make_uint4(pack_h2(v[0], v[1]), pack_h2(v[2], v[3]),
                                 pack_h2(v[4], v[5]), pack_h2(v[6], v[7]));
            *reinterpret_cast<uint4*>(smc + APX_B + (wn * 4 + mf) * 512 + lane * 16) = u;
        }
    }
    __syncthreads();   // x pack + w2 + outs visible to all warps

    // B tile base (uint4 granularity, +lane) for tile t
    auto bbase = [&](int t) -> const uint4* {
        const __half* gsrc;
        if (t < 8) {
            int c = t >> 2, kt = t & 3;
            gsrc = g_Wp0 + ((((size_t)d * 2 + c) * 4 + kt) * 1024) * 8;
        } else {
            int u = t - 8;
            int c = u >> 4, kt = u & 15;
            gsrc = g_Wp1 + ((((size_t)d * 2 + c) * 16 + kt) * 1024) * 8;
        }
        return reinterpret_cast<const uint4*>(gsrc) + lane;
    };
    // stage this warp's 2KB B tile for t into slot (t&1) of its private ring
    const uint32_t bwarp = sb + BSTG_B + (uint32_t)wn * 4096 + (uint32_t)lane * 16;
    auto bstage = [&](int t) {
        const uint4* gsrc = bbase(t);
        uint32_t dstb = bwarp + (uint32_t)(t & 1) * 2048;
#pragma unroll
        for (int i = 0; i < 4; i++)    // i = s*2 + p
            CP_ASYNC16(dstb + i * 512, gsrc + ((i >> 1) * 16 + wn * 2 + (i & 1)) * 32);
        CP_COMMIT();
    };

    bstage(0);

    float acc[4][4][4];                 // 64 rows (4 mf) x 32 cols (4 n8)
    float pr[8] = {0.f,0.f,0.f,0.f,0.f,0.f,0.f,0.f};

#pragma unroll 1
    for (int t = 0; t < NTILES; t++) {
        CP_WAIT0();        // stage(t) complete (issued a full tile ago)
        __syncwarp();
        if (t + 1 < NTILES) bstage(t + 1);   // full-tile prefetch distance, other slot

        bool first = (t < 8) ? ((t & 3) == 0) : (((t - 8) & 15) == 0);
        if (first) {
#pragma unroll
            for (int mf = 0; mf < 4; mf++)
#pragma unroll
                for (int s = 0; s < 4; s++)
#pragma unroll
                    for (int j = 0; j < 4; j++) acc[mf][s][j] = 0.f;
        }

        const int abase = (t < 8) ? (APX_B + (t & 3) * 4096)
                                  : (APH_B + ((t - 8) & 15) * 4096);
        const char* bslot = smc + BSTG_B + wn * 4096 + (t & 1) * 2048;

#pragma unroll
        for (int ks = 0; ks < 2; ks++) {
            uint4 a[4];
#pragma unroll
            for (int mf = 0; mf < 4; mf++)
                a[mf] = *reinterpret_cast<const uint4*>(
                    smc + abase + ks * 2048 + mf * 512 + lane * 16);
#pragma unroll
            for (int p = 0; p < 2; p++) {
                uint4 b = *reinterpret_cast<const uint4*>(
                    bslot + ((ks * 2 + p) * 32 + lane) * 16);
#pragma unroll
                for (int mf = 0; mf < 4; mf++) {
                    mma_f16(acc[mf][2 * p],     a[mf].x, a[mf].y, a[mf].z, a[mf].w, b.x, b.y);
                    mma_f16(acc[mf][2 * p + 1], a[mf].x, a[mf].y, a[mf].z, a[mf].w, b.z, b.w);
                }
            }
        }

        // L0 chunk epilogue: leaky -> fp16 -> APH fragment-major (conflict-free STS.128)
        if (t == 3 || t == 7) {
            if (t == 7) __syncthreads();   // all warps done reading aliased APX region
            int c = t >> 2;
#pragma unroll
            for (int mf = 0; mf < 4; mf++) {
#pragma unroll
                for (int p = 0; p < 2; p++) {
                    int K = c * 16 + wn * 2 + p;
                    int se = 2 * p, so = 2 * p + 1;
                    uint4 u = make_uint4(
                        pack_h2(leaky(acc[mf][se][0]), leaky(acc[mf][se][1])),
                        pack_h2(leaky(acc[mf][se][2]), leaky(acc[mf][se][3])),
                        pack_h2(leaky(acc[mf][so][0]), leaky(acc[mf][so][1])),
                        pack_h2(leaky(acc[mf][so][2]), leaky(acc[mf][so][3])));
                    *reinterpret_cast<uint4*>(
                        smc + APH_B + (K * 4 + mf) * 512 + lane * 16) = u;
                }
            }
            if (t == 7) __syncthreads();   // h1 complete before L1 A-reads
        }
        // L1 chunk epilogue: fused layer-2 dot (fp32)
        if (t == 23 || t == 39) {
            int c = (t - 8) >> 4;
#pragma unroll
            for (int mf = 0; mf < 4; mf++)
#pragma unroll
                for (int s = 0; s < 4; s++) {
                    int n = c * 256 + wn * 32 + 8 * s + 2 * t4;
                    float w2a = smf[W2_B / 4 + n], w2b = smf[W2_B / 4 + n + 1];
                    pr[mf * 2 + 0] += leaky(acc[mf][s][0]) * w2a + leaky(acc[mf][s][1]) * w2b;
                    pr[mf * 2 + 1] += leaky(acc[mf][s][2]) * w2a + leaky(acc[mf][s][3]) * w2b;
                }
        }
    }

#pragma unroll
    for (int j = 0; j < 8; j++) {
        pr[j] += __shfl_xor_sync(0xffffffffu, pr[j], 1);
        pr[j] += __shfl_xor_sync(0xffffffffu, pr[j], 2);
    }
    if (t4 == 0) {
#pragma unroll
        for (int mf = 0; mf < 4; mf++) {
            int R = mf * 16;
            atomicAdd(&smf[OUTS_B / 4 + R + g], pr[mf * 2 + 0]);
            atomicAdd(&smf[OUTS_B / 4 + R + g + 8], pr[mf * 2 + 1]);
        }
    }
    __syncthreads();
    if (tid < TM)
        out[(size_t)(n0 + tid) * DNODES + d] = smf[OUTS_B / 4 + tid];
}

extern "C" void kernel_launch(void* const* d_in, const int* in_sizes, int n_in,
                              void* d_out, int out_size) {
    (void)in_sizes; (void)n_in; (void)out_size;
    const float* x  = (const float*)d_in[0];
    const float* W0 = (const float*)d_in[1];
    const float* W1 = (const float*)d_in[2];
    const float* W2 = (const float*)d_in[3];
    float* out = (float*)d_out;

    pack_all<<<NB0H + NB1H, 256>>>(W0, W1);

    cudaFuncSetAttribute(grandag_f16_kernel,
                         cudaFuncAttributeMaxDynamicSharedMemorySize, SMEMB);
    dim3 grid(NSAMP / TM, DNODES);   // x fastest: same-d blocks co-resident (L2/L1 weight reuse)
    grandag_f16_kernel<<<grid, THREADS, SMEMB>>>(x, W2, out);
}